// round 11
// baseline (speedup 1.0000x reference)
#include <cuda_runtime.h>
#include <math.h>

#define BB 16
#define HW 65536            // 256*256
#define NPIX (BB*HW)        // 1048576
#define WPR 8               // u32 words per row
#define WPS 2048            // words per sample
#define NWORDS 32768
#define WLCAP 65536

#define TPB 256
#define NB 1024             // 1024 px per block (4 rows)
#define NTAIL 64            // last 64 blocks run phase 2 (1/4 sample each)

// ---- device scratch (allocation-free). Reset by finalize each replay. ----
__device__ unsigned g_posbits[NWORDS];
__device__ unsigned g_t1bits[NWORDS];
__device__ double g_ce;
__device__ int    g_hard_i, g_t_i, g_inter_i;
__device__ double g_res[BB];
__device__ int    g_haspos[BB];
__device__ int    g_hasneg[BB];
__device__ unsigned g_ticket;
__device__ unsigned g_ticket2;
__device__ int    g_wl_n;
__device__ int    g_wl[WLCAP];

// ---------------------------------------------------------------------------
// Exact fallback (rare; runs in the single finalize block only)
// ---------------------------------------------------------------------------
__device__ __forceinline__ int row_mindx(const unsigned* __restrict__ row, int j, unsigned inv) {
    int wj = j >> 5, off = j & 31;
    int best = 30000;
    unsigned m = (row[wj] ^ inv) >> off;
    if (m) best = __ffs(m) - 1;
    else {
        for (int w = wj + 1; w < WPR; ++w) {
            unsigned x = row[w] ^ inv;
            if (x) { best = 32 * (w - wj) - off + __ffs(x) - 1; break; }
        }
    }
    unsigned ml = (row[wj] ^ inv) << (31 - off);
    if (ml) { int d = __clz(ml); best = min(best, d); }
    else {
        for (int w = wj - 1; w >= 0; --w) {
            unsigned x = row[w] ^ inv;
            if (x) { int d = j - (32 * w + 31 - __clz(x)); best = min(best, d); break; }
        }
    }
    return best;
}

__device__ double fb_contrib(const unsigned* __restrict__ bp, int i, int j, int mybit,
                             int haspos, int hasneg) {
    float d;
    if (!haspos || !hasneg) {
        d = 1.0e9f;                      // reference BIG
    } else {
        unsigned inv = mybit ? 0xffffffffu : 0u;
        int best2 = 1 << 30;
        for (int dy = 0; dy < 256; ++dy) {
            int dy2 = dy * dy;
            if (dy2 >= best2) break;
            int up = i - dy, dn = i + dy;
            if (up >= 0) {
                int dx = row_mindx(bp + up * WPR, j, inv);
                int d2 = dy2 + dx * dx;
                if (d2 < best2) best2 = d2;
            }
            if (dy && dn < 256) {
                int dx = row_mindx(bp + dn * WPR, j, inv);
                int d2 = dy2 + dx * dx;
                if (d2 < best2) best2 = d2;
            }
        }
        d = sqrtf((float)best2);
    }
    return mybit ? -(double)(d - 1.0f) : (double)d;
}

// ---------------------------------------------------------------------------
// Phase-2 contribution for one bitboard word (reads L2-resident bitboards).
// ---------------------------------------------------------------------------
__device__ __forceinline__ float word_contrib(int b, int w) {
    const unsigned* __restrict__ bp = g_posbits + b * WPS;
    const unsigned* __restrict__ tp = g_t1bits  + b * WPS;
    int i = w >> 3, wc = w & 7;

    unsigned P  = __ldg(bp + i * WPR + wc);
    unsigned T1 = __ldg(tp + i * WPR + wc);

    unsigned lm1 = (wc == 0) ? 0xfffffffeu : 0xffffffffu;
    unsigned rm1 = (wc == 7) ? 0x7fffffffu : 0xffffffffu;
    unsigned lm2 = (wc == 0) ? 0xfffffffcu : 0xffffffffu;
    unsigned rm2 = (wc == 7) ? 0x3fffffffu : 0xffffffffu;
    unsigned vu1 = (i >= 1)   ? 0xffffffffu : 0u;
    unsigned vu2 = (i >= 2)   ? 0xffffffffu : 0u;
    unsigned vd1 = (i <= 254) ? 0xffffffffu : 0u;
    unsigned vd2 = (i <= 253) ? 0xffffffffu : 0u;
    int iu1 = max(i - 1, 0), iu2 = max(i - 2, 0);
    int id1 = min(i + 1, 255), id2 = min(i + 2, 255);

    #define ROWX(r, XM, X1L, X1R, X2L, X2R) {                        \
        unsigned Lw = (wc > 0) ? __ldg(bp + (r) * WPR + wc - 1) : 0u;\
        unsigned Mw = __ldg(bp + (r) * WPR + wc);                    \
        unsigned Rw = (wc < 7) ? __ldg(bp + (r) * WPR + wc + 1) : 0u;\
        XM  = Mw ^ P;                                                \
        X1L = __funnelshift_l(Lw, Mw, 1) ^ P;                        \
        X1R = __funnelshift_r(Mw, Rw, 1) ^ P;                        \
        X2L = __funnelshift_l(Lw, Mw, 2) ^ P;                        \
        X2R = __funnelshift_r(Mw, Rw, 2) ^ P; }

    unsigned m0, l10, r10, l20, r20;      ROWX(i,   m0,  l10,  r10,  l20,  r20)
    unsigned mu1, l1u1, r1u1, l2u1, r2u1; ROWX(iu1, mu1, l1u1, r1u1, l2u1, r2u1)
    unsigned md1, l1d1, r1d1, l2d1, r2d1; ROWX(id1, md1, l1d1, r1d1, l2d1, r2d1)
    unsigned mu2, l1u2, r1u2, l2u2, r2u2; ROWX(iu2, mu2, l1u2, r1u2, l2u2, r2u2)
    unsigned md2, l1d2, r1d2, l2d2, r2d2; ROWX(id2, md2, l1d2, r1d2, l2d2, r2d2)
    #undef ROWX

    unsigned D1 = (l10 & lm1) | (r10 & rm1) | (mu1 & vu1) | (md1 & vd1);
    unsigned D2 = (((l1u1 & lm1) | (r1u1 & rm1)) & vu1)
                | (((l1d1 & lm1) | (r1d1 & rm1)) & vd1);
    unsigned D4 = (l20 & lm2) | (r20 & rm2) | (mu2 & vu2) | (md2 & vd2);
    unsigned D5 = (((l2u1 & lm2) | (r2u1 & rm2)) & vu1)
                | (((l2d1 & lm2) | (r2d1 & rm2)) & vd1)
                | (((l1u2 & lm1) | (r1u2 & rm1)) & vu2)
                | (((l1d2 & lm1) | (r1d2 & rm1)) & vd2);
    unsigned D8 = (((l2u2 & lm2) | (r2u2 & rm2)) & vu2)
                | (((l2d2 & lm2) | (r2d2 & rm2)) & vd2);

    unsigned A1m = D1 & T1;
    unsigned R2m = T1 & ~D1;   unsigned A2m = D2 & R2m;
    unsigned R4m = R2m & ~D2;  unsigned A4m = D4 & R4m;
    unsigned R5m = R4m & ~D4;  unsigned A5m = D5 & R5m;
    unsigned R8m = R5m & ~D5;  unsigned A8m = D8 & R8m;
    unsigned U   = R8m & ~D8;

    const float S2 = 1.41421354f;
    const float S5 = 2.23606801f;
    const float S8 = 2.82842708f;

    float c;
    c  = (float)__popc(A1m & ~P);
    c += (float)__popc(A2m & ~P) * S2 - (float)__popc(A2m & P) * (S2 - 1.0f);
    c += (float)__popc(A4m & ~P) * 2.0f - (float)__popc(A4m & P) * 1.0f;
    c += (float)__popc(A5m & ~P) * S5 - (float)__popc(A5m & P) * (S5 - 1.0f);
    c += (float)__popc(A8m & ~P) * S8 - (float)__popc(A8m & P) * (S8 - 1.0f);

    while (U) {   // rare: defer to worklist for the finalize block
        int jb = __ffs(U) - 1; U &= U - 1;
        int j = wc * 32 + jb;
        int mybit = (P >> jb) & 1;
        int slot = atomicAdd(&g_wl_n, 1);
        if (slot < WLCAP)
            g_wl[slot] = (b << 17) | (i << 9) | (j << 1) | mybit;
    }
    return c;
}

// ---------------------------------------------------------------------------
// Fused kernel: 1024-block ballot streamer + ticket-gated 64-block phase-2 tail
// ---------------------------------------------------------------------------
__global__ __launch_bounds__(TPB)
void k_fused(const float* __restrict__ inp, const int* __restrict__ tgt,
             float* __restrict__ out, int out_size) {
    __shared__ float sce[8];
    __shared__ int   scnt[8], sfl[8];
    __shared__ unsigned s_tk;
    __shared__ float s_pc[8];
    __shared__ bool  s_last;

    int tid = threadIdx.x, w = tid >> 5, l = tid & 31;
    int base = blockIdx.x * 1024 + w * 128;   // warp's 128-px span
    int s    = blockIdx.x >> 6;               // 64 blocks per sample
    int hwb  = base & 65535;

    const float* c0 = inp + (size_t)(s * 2) * HW;
    const float* c1 = c0 + HW;
    const int*   tg = tgt + (s << 16);

    // ================= Phase 1: streaming prep (proven 5.8us shape) =========
    float ces = 0.0f;
    int hard = 0, tcnt = 0, inter = 0;
    unsigned anyp = 0u, alln = 0xffffffffu;

    #pragma unroll
    for (int it = 0; it < 4; ++it) {
        int hw = hwb + it * 32 + l;
        float x0 = __ldg(c0 + hw);
        float x1 = __ldg(c1 + hw);
        int   t  = __ldg(tg + hw);
        float lse = fmaxf(x0, x1) + __logf(1.0f + __expf(-fabsf(x1 - x0)));
        ces += lse - ((t == 1) ? x1 : x0);

        unsigned bp_ = __ballot_sync(0xffffffffu, x1 >  x0);
        unsigned bh  = __ballot_sync(0xffffffffu, x1 >= x0);
        unsigned bt  = __ballot_sync(0xffffffffu, t == 1);
        hard  += __popc(bh);
        tcnt  += __popc(bt);
        inter += __popc(bh & bt);
        anyp  |= bp_;
        alln  &= bp_;
        if (l == it) {
            int wi = (base >> 5) + it;
            g_posbits[wi] = bp_;
            g_t1bits[wi]  = bt;
        }
    }

    #pragma unroll
    for (int off = 16; off > 0; off >>= 1)
        ces += __shfl_xor_sync(0xffffffffu, ces, off);

    unsigned cnt = (unsigned)hard | ((unsigned)tcnt << 10) | ((unsigned)inter << 20);
    if (l == 0) {
        sce[w]  = ces;
        scnt[w] = (int)cnt;
        sfl[w]  = (anyp ? 1 : 0) | ((alln != 0xffffffffu) ? 2 : 0);
    }
    __syncthreads();
    if (tid == 0) {
        float bce = 0.0f; int bh = 0, bt2 = 0, bi = 0, bfl = 0;
        #pragma unroll
        for (int k = 0; k < 8; ++k) {
            bce += sce[k];
            unsigned c = (unsigned)scnt[k];
            bh += (int)(c & 1023u); bt2 += (int)((c >> 10) & 1023u); bi += (int)(c >> 20);
            bfl |= sfl[k];
        }
        atomicAdd(&g_ce, (double)bce);
        atomicAdd(&g_hard_i,  bh);
        atomicAdd(&g_t_i,     bt2);
        atomicAdd(&g_inter_i, bi);
        if (bfl & 1) g_haspos[s] = 1;
        if (bfl & 2) g_hasneg[s] = 1;

        __threadfence();
        s_tk = atomicAdd(&g_ticket, 1u);
    }
    __syncthreads();
    unsigned tk = s_tk;
    if (tk < NB - NTAIL) return;      // most blocks retire immediately

    // ================= Tail: last 64 ticket-holders run phase 2 ============
    if (tid == 0) {
        while (*((volatile unsigned*)&g_ticket) < NB) __nanosleep(64);
        __threadfence();
    }
    __syncthreads();

    int tb  = (int)tk - (NB - NTAIL);   // 0..63
    int sq  = tb >> 2;                  // sample
    int qtr = tb & 3;                   // quarter

    float contrib = 0.0f;
    int w0 = qtr * 512 + tid * 2;       // two words per thread
    contrib += word_contrib(sq, w0);
    contrib += word_contrib(sq, w0 + 1);

    #pragma unroll
    for (int off = 16; off > 0; off >>= 1)
        contrib += __shfl_xor_sync(0xffffffffu, contrib, off);
    if (l == 0) s_pc[w] = contrib;
    __syncthreads();

    if (tid == 0) {
        float bc = 0.0f;
        #pragma unroll
        for (int k = 0; k < 8; ++k) bc += s_pc[k];
        atomicAdd(&g_res[sq], (double)bc);
        __threadfence();
        unsigned tk2 = atomicAdd(&g_ticket2, 1u);
        s_last = (tk2 == NTAIL - 1);
    }
    __syncthreads();

    // ================= Finalize in the very last tail block ================
    if (s_last) {
        if (tid == 0) __threadfence();
        __syncthreads();
        int n = g_wl_n; if (n > WLCAP) n = WLCAP;
        for (int k = tid; k < n; k += TPB) {
            int e = g_wl[k];
            int es = e >> 17, ei = (e >> 9) & 255, ej = (e >> 1) & 255, eb = e & 1;
            double v = fb_contrib(g_posbits + es * WPS, ei, ej, eb,
                                  g_haspos[es], g_hasneg[es]);
            atomicAdd(&g_res[es], v);
        }
        __syncthreads();
        if (tid == 0) {
            double ce = g_ce / (double)NPIX;
            double dice = 1.0 - (2.0 * (double)g_inter_i + 1.0)
                              / ((double)g_hard_i + (double)g_t_i + 1.0);
            double lb = 0.0;
            #pragma unroll
            for (int q = 0; q < BB; ++q)
                if (g_haspos[q]) lb += g_res[q] / (double)HW;
            float r = (float)(ce + dice + lb * lb);
            for (int k = 0; k < out_size; ++k) out[k] = r;

            g_ce = 0.0; g_hard_i = 0; g_t_i = 0; g_inter_i = 0;
            #pragma unroll
            for (int q = 0; q < BB; ++q) { g_res[q] = 0.0; g_haspos[q] = 0; g_hasneg[q] = 0; }
            g_ticket = 0u; g_ticket2 = 0u; g_wl_n = 0;
        }
    }
}

extern "C" void kernel_launch(void* const* d_in, const int* in_sizes, int n_in,
                              void* d_out, int out_size) {
    const float* inputs  = (const float*)d_in[0];   // (16,2,256,256) f32
    const int*   targets = (const int*)  d_in[1];   // (16,256,256)   i32
    k_fused<<<NB, TPB>>>(inputs, targets, (float*)d_out, out_size);
}

// round 12
// speedup vs baseline: 1.0890x; 1.0890x over previous
#include <cuda_runtime.h>
#include <math.h>

#define BB 16
#define HW 65536            // 256*256
#define NPIX (BB*HW)        // 1048576
#define WPR 8               // u32 words per row
#define WPS 2048            // words per sample
#define NWORDS 32768
#define WLCAP 65536

#define TPB1 256
#define NB1 1024            // K1: 1024 px per block, 64 blocks/sample
#define TPB2 128
#define NB2 (NWORDS/TPB2)   // 256

// Interleaved bitboard: g_bits[2*w] = pos word, g_bits[2*w+1] = t1 word.
__device__ unsigned g_bits[2 * NWORDS];
__device__ double g_ce;
__device__ int    g_hard_i, g_t_i, g_inter_i;
__device__ double g_res[BB];
__device__ int    g_haspos[BB];
__device__ int    g_hasneg[BB];
__device__ unsigned g_ticket;
__device__ int    g_wl_n;
__device__ int    g_wl[WLCAP];

// ---------------------------------------------------------------------------
// Exact fallback (rare; runs in K2's last block). Stride-2 word access.
// ---------------------------------------------------------------------------
__device__ __forceinline__ unsigned posw(const unsigned* __restrict__ sb, int i, int w) {
    return sb[(i * WPR + w) * 2];
}

__device__ __forceinline__ int row_mindx(const unsigned* __restrict__ sb, int i, int j, unsigned inv) {
    int wj = j >> 5, off = j & 31;
    int best = 30000;
    unsigned m = (posw(sb, i, wj) ^ inv) >> off;
    if (m) best = __ffs(m) - 1;
    else {
        for (int w = wj + 1; w < WPR; ++w) {
            unsigned x = posw(sb, i, w) ^ inv;
            if (x) { best = 32 * (w - wj) - off + __ffs(x) - 1; break; }
        }
    }
    unsigned ml = (posw(sb, i, wj) ^ inv) << (31 - off);
    if (ml) { int d = __clz(ml); best = min(best, d); }
    else {
        for (int w = wj - 1; w >= 0; --w) {
            unsigned x = posw(sb, i, w) ^ inv;
            if (x) { int d = j - (32 * w + 31 - __clz(x)); best = min(best, d); break; }
        }
    }
    return best;
}

__device__ double fb_contrib(const unsigned* __restrict__ sb, int i, int j, int mybit,
                             int haspos, int hasneg) {
    float d;
    if (!haspos || !hasneg) {
        d = 1.0e9f;                      // reference BIG
    } else {
        unsigned inv = mybit ? 0xffffffffu : 0u;
        int best2 = 1 << 30;
        for (int dy = 0; dy < 256; ++dy) {
            int dy2 = dy * dy;
            if (dy2 >= best2) break;
            int up = i - dy, dn = i + dy;
            if (up >= 0) {
                int dx = row_mindx(sb, up, j, inv);
                int d2 = dy2 + dx * dx;
                if (d2 < best2) best2 = d2;
            }
            if (dy && dn < 256) {
                int dx = row_mindx(sb, dn, j, inv);
                int d2 = dy2 + dx * dx;
                if (d2 < best2) best2 = d2;
            }
        }
        d = sqrtf((float)best2);
    }
    return mybit ? -(double)(d - 1.0f) : (double)d;
}

// ---------------------------------------------------------------------------
// K1: high-MLP prep. 4 px/thread via 3 up-front LDG.128; shuffle bit assembly.
// ---------------------------------------------------------------------------
__global__ __launch_bounds__(TPB1)
void k_prep(const float* __restrict__ inp, const int* __restrict__ tgt) {
    int tid = threadIdx.x, w = tid >> 5, l = tid & 31;
    int px  = blockIdx.x * 1024 + tid * 4;    // 4 consecutive pixels
    int s   = blockIdx.x >> 6;                // 64 blocks per sample
    int hw  = px & 65535;

    const float* c0 = inp + (size_t)(s * 2) * HW;
    const float* c1 = c0 + HW;

    // all loads issued before any dependent math (max MLP)
    float4 a = *(const float4*)(c0 + hw);
    float4 c = *(const float4*)(c1 + hw);
    int4   t = *(const int4*)(tgt + px);

    float ces = 0.0f;
    unsigned pn = 0, hn = 0, tn = 0;
    #define ELEM(K, X0, X1, T) {                                   \
        float x0 = (X0), x1 = (X1); int tt = (T);                  \
        float lse = fmaxf(x0, x1) + __logf(1.0f + __expf(-fabsf(x1 - x0))); \
        ces += lse - ((tt == 1) ? x1 : x0);                        \
        pn |= ((unsigned)(x1 >  x0)) << (K);                       \
        hn |= ((unsigned)(x1 >= x0)) << (K);                       \
        tn |= ((unsigned)(tt == 1))  << (K); }
    ELEM(0, a.x, c.x, t.x)
    ELEM(1, a.y, c.y, t.y)
    ELEM(2, a.z, c.z, t.z)
    ELEM(3, a.w, c.w, t.w)
    #undef ELEM

    // counts from nibbles
    int hard = __popc(hn), tcnt = __popc(tn), inter = __popc(hn & tn);

    // 3-step shuffle assembly: lanes l%8==0 end with (pos word | t1 word<<32)
    unsigned long long v = (unsigned long long)pn | ((unsigned long long)tn << 32);
    v |= __shfl_xor_sync(0xffffffffu, v, 1) << 4;
    v |= __shfl_xor_sync(0xffffffffu, v, 2) << 8;
    v |= __shfl_xor_sync(0xffffffffu, v, 4) << 16;
    if ((l & 7) == 0) {
        int wi = (blockIdx.x * 1024 + w * 128 + (l >> 3) * 32) >> 5;
        *(uint2*)(g_bits + 2 * wi) = make_uint2((unsigned)v, (unsigned)(v >> 32));
    }

    // reductions: packed REDUX for counts, ballots for flags, shfl for CE
    unsigned cnt = (unsigned)hard | ((unsigned)tcnt << 10) | ((unsigned)inter << 20);
    unsigned wcnt = __reduce_add_sync(0xffffffffu, cnt);
    unsigned bpos = __ballot_sync(0xffffffffu, pn != 0u);
    unsigned bneg = __ballot_sync(0xffffffffu, pn != 0xFu);
    #pragma unroll
    for (int off = 16; off > 0; off >>= 1)
        ces += __shfl_xor_sync(0xffffffffu, ces, off);

    __shared__ float sce[8];
    __shared__ int   scnt[8], sfl[8];
    if (l == 0) {
        sce[w]  = ces;
        scnt[w] = (int)wcnt;
        sfl[w]  = (bpos ? 1 : 0) | (bneg ? 2 : 0);
    }
    __syncthreads();
    if (tid == 0) {
        float bce = 0.0f; int bh = 0, bt = 0, bi = 0, bfl = 0;
        #pragma unroll
        for (int k = 0; k < 8; ++k) {
            bce += sce[k];
            unsigned cc = (unsigned)scnt[k];
            bh += (int)(cc & 1023u); bt += (int)((cc >> 10) & 1023u); bi += (int)(cc >> 20);
            bfl |= sfl[k];
        }
        atomicAdd(&g_ce, (double)bce);
        atomicAdd(&g_hard_i,  bh);
        atomicAdd(&g_t_i,     bt);
        atomicAdd(&g_inter_i, bi);
        if (bfl & 1) g_haspos[s] = 1;
        if (bfl & 2) g_hasneg[s] = 1;
    }
}

// ---------------------------------------------------------------------------
// K2: 5x5 bit-parallel boundary over interleaved bitboards + finalize.
// ---------------------------------------------------------------------------
__global__ __launch_bounds__(TPB2)
void k_bnd(float* __restrict__ out, int out_size) {
    int tid = threadIdx.x;
    int tw  = blockIdx.x * TPB2 + tid;
    int b   = tw >> 11;
    int w   = tw & 2047;
    int i   = w >> 3, wc = w & 7;

    const unsigned* __restrict__ sb = g_bits + b * WPS * 2;

    uint2 self = *(const uint2*)(sb + (i * WPR + wc) * 2);
    unsigned P  = self.x;
    unsigned T1 = self.y;

    unsigned lm1 = (wc == 0) ? 0xfffffffeu : 0xffffffffu;
    unsigned rm1 = (wc == 7) ? 0x7fffffffu : 0xffffffffu;
    unsigned lm2 = (wc == 0) ? 0xfffffffcu : 0xffffffffu;
    unsigned rm2 = (wc == 7) ? 0x3fffffffu : 0xffffffffu;
    unsigned vu1 = (i >= 1)   ? 0xffffffffu : 0u;
    unsigned vu2 = (i >= 2)   ? 0xffffffffu : 0u;
    unsigned vd1 = (i <= 254) ? 0xffffffffu : 0u;
    unsigned vd2 = (i <= 253) ? 0xffffffffu : 0u;
    int iu1 = max(i - 1, 0), iu2 = max(i - 2, 0);
    int id1 = min(i + 1, 255), id2 = min(i + 2, 255);

    #define ROWX(r, XM, X1L, X1R, X2L, X2R) {                              \
        unsigned Lw = (wc > 0) ? __ldg(sb + ((r) * WPR + wc - 1) * 2) : 0u;\
        unsigned Mw = __ldg(sb + ((r) * WPR + wc) * 2);                    \
        unsigned Rw = (wc < 7) ? __ldg(sb + ((r) * WPR + wc + 1) * 2) : 0u;\
        XM  = Mw ^ P;                                                      \
        X1L = __funnelshift_l(Lw, Mw, 1) ^ P;                              \
        X1R = __funnelshift_r(Mw, Rw, 1) ^ P;                              \
        X2L = __funnelshift_l(Lw, Mw, 2) ^ P;                              \
        X2R = __funnelshift_r(Mw, Rw, 2) ^ P; }

    unsigned m0, l10, r10, l20, r20;      ROWX(i,   m0,  l10,  r10,  l20,  r20)
    unsigned mu1, l1u1, r1u1, l2u1, r2u1; ROWX(iu1, mu1, l1u1, r1u1, l2u1, r2u1)
    unsigned md1, l1d1, r1d1, l2d1, r2d1; ROWX(id1, md1, l1d1, r1d1, l2d1, r2d1)
    unsigned mu2, l1u2, r1u2, l2u2, r2u2; ROWX(iu2, mu2, l1u2, r1u2, l2u2, r2u2)
    unsigned md2, l1d2, r1d2, l2d2, r2d2; ROWX(id2, md2, l1d2, r1d2, l2d2, r2d2)
    #undef ROWX

    unsigned D1 = (l10 & lm1) | (r10 & rm1) | (mu1 & vu1) | (md1 & vd1);
    unsigned D2 = (((l1u1 & lm1) | (r1u1 & rm1)) & vu1)
                | (((l1d1 & lm1) | (r1d1 & rm1)) & vd1);
    unsigned D4 = (l20 & lm2) | (r20 & rm2) | (mu2 & vu2) | (md2 & vd2);
    unsigned D5 = (((l2u1 & lm2) | (r2u1 & rm2)) & vu1)
                | (((l2d1 & lm2) | (r2d1 & rm2)) & vd1)
                | (((l1u2 & lm1) | (r1u2 & rm1)) & vu2)
                | (((l1d2 & lm1) | (r1d2 & rm1)) & vd2);
    unsigned D8 = (((l2u2 & lm2) | (r2u2 & rm2)) & vu2)
                | (((l2d2 & lm2) | (r2d2 & rm2)) & vd2);

    unsigned A1m = D1 & T1;
    unsigned R2m = T1 & ~D1;   unsigned A2m = D2 & R2m;
    unsigned R4m = R2m & ~D2;  unsigned A4m = D4 & R4m;
    unsigned R5m = R4m & ~D4;  unsigned A5m = D5 & R5m;
    unsigned R8m = R5m & ~D5;  unsigned A8m = D8 & R8m;
    unsigned U   = R8m & ~D8;

    const float S2 = 1.41421354f;
    const float S5 = 2.23606801f;
    const float S8 = 2.82842708f;

    float contrib;
    contrib  = (float)__popc(A1m & ~P);
    contrib += (float)__popc(A2m & ~P) * S2 - (float)__popc(A2m & P) * (S2 - 1.0f);
    contrib += (float)__popc(A4m & ~P) * 2.0f - (float)__popc(A4m & P) * 1.0f;
    contrib += (float)__popc(A5m & ~P) * S5 - (float)__popc(A5m & P) * (S5 - 1.0f);
    contrib += (float)__popc(A8m & ~P) * S8 - (float)__popc(A8m & P) * (S8 - 1.0f);

    while (U) {   // rare: defer to worklist for the final block
        int jb = __ffs(U) - 1; U &= U - 1;
        int j = wc * 32 + jb;
        int mybit = (P >> jb) & 1;
        int slot = atomicAdd(&g_wl_n, 1);
        if (slot < WLCAP)
            g_wl[slot] = (b << 17) | (i << 9) | (j << 1) | mybit;
    }

    #pragma unroll
    for (int off = 16; off > 0; off >>= 1)
        contrib += __shfl_xor_sync(0xffffffffu, contrib, off);
    __shared__ float s_c[4];
    int wid = tid >> 5;
    if ((tid & 31) == 0) s_c[wid] = contrib;
    __syncthreads();

    __shared__ bool s_last;
    if (tid == 0) {
        atomicAdd(&g_res[b], (double)(s_c[0] + s_c[1] + s_c[2] + s_c[3]));
        __threadfence();
        unsigned tk = atomicAdd(&g_ticket, 1u);
        s_last = (tk == NB2 - 1);
    }
    __syncthreads();

    if (s_last) {
        if (tid == 0) __threadfence();
        __syncthreads();
        int n = g_wl_n; if (n > WLCAP) n = WLCAP;
        for (int k = tid; k < n; k += TPB2) {
            int e = g_wl[k];
            int es = e >> 17, ei = (e >> 9) & 255, ej = (e >> 1) & 255, eb = e & 1;
            double v = fb_contrib(g_bits + es * WPS * 2, ei, ej, eb,
                                  g_haspos[es], g_hasneg[es]);
            atomicAdd(&g_res[es], v);
        }
        __syncthreads();
        if (tid == 0) {
            double ce = g_ce / (double)NPIX;
            double dice = 1.0 - (2.0 * (double)g_inter_i + 1.0)
                              / ((double)g_hard_i + (double)g_t_i + 1.0);
            double lb = 0.0;
            #pragma unroll
            for (int q = 0; q < BB; ++q)
                if (g_haspos[q]) lb += g_res[q] / (double)HW;
            float r = (float)(ce + dice + lb * lb);
            for (int k = 0; k < out_size; ++k) out[k] = r;

            g_ce = 0.0; g_hard_i = 0; g_t_i = 0; g_inter_i = 0;
            #pragma unroll
            for (int q = 0; q < BB; ++q) { g_res[q] = 0.0; g_haspos[q] = 0; g_hasneg[q] = 0; }
            g_ticket = 0u; g_wl_n = 0;
        }
    }
}

extern "C" void kernel_launch(void* const* d_in, const int* in_sizes, int n_in,
                              void* d_out, int out_size) {
    const float* inputs  = (const float*)d_in[0];   // (16,2,256,256) f32
    const int*   targets = (const int*)  d_in[1];   // (16,256,256)   i32
    k_prep<<<NB1, TPB1>>>(inputs, targets);
    k_bnd<<<NB2, TPB2>>>((float*)d_out, out_size);
}